// round 11
// baseline (speedup 1.0000x reference)
#include <cuda_runtime.h>
#include <cuda_fp16.h>
#include <cstdint>
#include <cstddef>

#define T_SEQ 512
#define BATCH 128
#define DIN   1024
#define DOUT  1024
#define N4    4096          // 4 gates * DOUT, gate-interleaved: n = unit*4 + gate
#define GRID_LSTM 128

// ---------------- static device scratch (no allocations allowed) ----------------
__device__ __align__(256) float  g_Z   [(size_t)T_SEQ * BATCH * N4]; // 1 GiB preactivations (+bias)
__device__ __align__(256) __half g_WxH [(size_t)N4 * DIN];           // packed fp16 x-weights
__device__ __align__(256) __half g_WhH [(size_t)N4 * DOUT];          // packed fp16 h-weights
__device__ __align__(256) float  g_bias[N4];
__device__ __align__(256) __half g_XhH [(size_t)T_SEQ * BATCH * DIN];// fp16 tokens
__device__ __align__(256) __half g_hH  [2][BATCH * DOUT];            // ping-pong hidden state fp16
__device__ unsigned g_bar2[2][32];                                   // per-mt-group barrier counters

// ---------------- helpers ----------------
__device__ __forceinline__ void cp16(void* smem_dst, const void* gsrc) {
    unsigned s = (unsigned)__cvta_generic_to_shared(smem_dst);
    asm volatile("cp.async.cg.shared.global [%0], [%1], 16;\n" :: "r"(s), "l"(gsrc));
}

__device__ __forceinline__ void ldsm4(unsigned& r0, unsigned& r1, unsigned& r2, unsigned& r3,
                                      uint32_t addr) {
    asm volatile("ldmatrix.sync.aligned.m8n8.x4.shared.b16 {%0,%1,%2,%3}, [%4];"
                 : "=r"(r0), "=r"(r1), "=r"(r2), "=r"(r3) : "r"(addr));
}

__device__ __forceinline__ void mma16(float* d, const unsigned* a, const unsigned* b) {
    asm volatile(
        "mma.sync.aligned.m16n8k16.row.col.f32.f16.f16.f32 "
        "{%0,%1,%2,%3}, {%4,%5,%6,%7}, {%8,%9}, {%0,%1,%2,%3};\n"
        : "+f"(d[0]), "+f"(d[1]), "+f"(d[2]), "+f"(d[3])
        : "r"(a[0]), "r"(a[1]), "r"(a[2]), "r"(a[3]), "r"(b[0]), "r"(b[1]));
}

// fp16-accumulate mma: C-frag = 2 regs (half2 row gid / row gid+8)
__device__ __forceinline__ void mma16h(unsigned* d, const unsigned* a, const unsigned* b) {
    asm volatile(
        "mma.sync.aligned.m16n8k16.row.col.f16.f16.f16.f16 "
        "{%0,%1}, {%2,%3,%4,%5}, {%6,%7}, {%0,%1};\n"
        : "+r"(d[0]), "+r"(d[1])
        : "r"(a[0]), "r"(a[1]), "r"(a[2]), "r"(a[3]), "r"(b[0]), "r"(b[1]));
}

__device__ __forceinline__ float sigm(float x) { return 1.f / (1.f + __expf(-x)); }

__device__ __forceinline__ uint32_t smem_u32(const void* p) {
    return (uint32_t)__cvta_generic_to_shared(p);
}

// ---------------- kernel 1: pack weights / convert tokens / reset state ----------------
__global__ void __launch_bounds__(256) pack_kernel(
    const float* __restrict__ tokens,
    const float* __restrict__ Wf, const float* __restrict__ bf,
    const float* __restrict__ Wi, const float* __restrict__ bi,
    const float* __restrict__ Wc, const float* __restrict__ bc,
    const float* __restrict__ Wo, const float* __restrict__ bo)
{
    size_t tid = (size_t)blockIdx.x * blockDim.x + threadIdx.x;
    size_t nth = (size_t)gridDim.x * blockDim.x;
    if (tid < 64) g_bar2[tid >> 5][tid & 31] = 0;   // reset barriers every launch (graph replays)

    for (size_t i = tid; i < (size_t)N4 * 1024; i += nth) {
        int n = (int)(i >> 10), k = (int)(i & 1023);
        int u = n >> 2, g = n & 3;
        const float* W = (g == 0) ? Wf : (g == 1) ? Wi : (g == 2) ? Wc : Wo;
        g_WxH[i] = __float2half_rn(W[(size_t)u * 2048 + k]);
        g_WhH[i] = __float2half_rn(W[(size_t)u * 2048 + 1024 + k]);
    }
    for (size_t i = tid; i < (size_t)N4; i += nth) {
        int u = (int)(i >> 2), g = (int)(i & 3);
        const float* bb = (g == 0) ? bf : (g == 1) ? bi : (g == 2) ? bc : bo;
        g_bias[i] = bb[u];
    }
    for (size_t i = tid; i < (size_t)T_SEQ * BATCH * DIN; i += nth)
        g_XhH[i] = __float2half_rn(tokens[i]);
    for (size_t i = tid; i < (size_t)BATCH * DOUT; i += nth)
        g_hH[0][i] = __float2half_rn(0.f);   // h0 = 0
}

// ---------------- kernel 2: fp16 mma (f16 accumulate, f32 promote): Z = X @ Wx^T + b ----
// CTA tile 128x64, 256 threads = 8 warps 4(M)x2(N); warp tile 32x32; K-chunk 64.
// f16 accumulation over K=32 (2 mmas), promoted into f32 accs. 2 CTAs/SM.
#define PC_SAS  72                       // halfs per smem row (64 data + 8 pad)
#define PC_AT   (128 * PC_SAS)           // A tile: 9216 halfs
#define PC_BT   (64 * PC_SAS)            // B tile: 4608 halfs
#define PC_BUF  (PC_AT + PC_BT)          // 13824 halfs per buffer
#define PC_SMEM (2 * PC_BUF * 2)         // 55296 bytes

__global__ void __launch_bounds__(256, 2) precompute_fp16() {
    extern __shared__ __half smH[];
    const int tid = threadIdx.x, lane = tid & 31, wid = tid >> 5;
    const int wm = wid >> 1, wn = wid & 1;       // 4(M) x 2(N)
    const int gid = lane >> 2, tig = lane & 3;
    const int bx = blockIdx.x;
    const int mt = bx >> 6, nt = bx & 63;        // nt fastest: A tile shared in L2
    const size_t m0 = (size_t)mt * 128;
    const int n0 = nt * 64;

    const __half* Ax = g_XhH + m0 * 1024;
    const __half* Bw = g_WxH + (size_t)n0 * 1024;
    const uint32_t smb = smem_u32(smH);

    // ldmatrix per-thread address components
    const int aR = (lane & 15), aK = ((lane >> 4) << 3);
    const int bR = (lane & 7) + ((lane >> 4) << 3), bK = ((lane >> 3) & 1) << 3;

    float    acc [2][4][4] = {};     // f32 accumulators
    unsigned acc16[2][4][2];         // f16 staging accumulators (K=32 windows)

    // chunk loader: A 128x64 (1024 cp16, 4/thr) + B 64x64 (512 cp16, 2/thr)
    #define PC_LOAD(buf, c) do {                                                   \
        __half* dA_ = smH + (buf) * PC_BUF;                                        \
        __half* dB_ = dA_ + PC_AT;                                                 \
        int k0_ = (c) * 64;                                                        \
        _Pragma("unroll")                                                          \
        for (int i_ = 0; i_ < 4; i_++) { int ix_ = tid + i_ * 256;                 \
            int r_ = ix_ >> 3, s_ = ix_ & 7;                                       \
            cp16(dA_ + r_ * PC_SAS + s_ * 8, Ax + (size_t)r_ * 1024 + k0_ + s_ * 8);} \
        _Pragma("unroll")                                                          \
        for (int i_ = 0; i_ < 2; i_++) { int ix_ = tid + i_ * 256;                 \
            int r_ = ix_ >> 3, s_ = ix_ & 7;                                       \
            cp16(dB_ + r_ * PC_SAS + s_ * 8, Bw + (size_t)r_ * 1024 + k0_ + s_ * 8);} \
        asm volatile("cp.async.commit_group;\n");                                  \
    } while (0)

    // promote f16 staging accs into f32 and clear
    #define PC_PROMOTE() do {                                                      \
        _Pragma("unroll")                                                          \
        for (int mi_ = 0; mi_ < 2; mi_++)                                          \
            _Pragma("unroll")                                                      \
            for (int ni_ = 0; ni_ < 4; ni_++) {                                    \
                float2 lo_ = __half22float2(*reinterpret_cast<__half2*>(&acc16[mi_][ni_][0])); \
                float2 hi_ = __half22float2(*reinterpret_cast<__half2*>(&acc16[mi_][ni_][1])); \
                acc[mi_][ni_][0] += lo_.x; acc[mi_][ni_][1] += lo_.y;              \
                acc[mi_][ni_][2] += hi_.x; acc[mi_][ni_][3] += hi_.y;              \
                acc16[mi_][ni_][0] = 0u;   acc16[mi_][ni_][1] = 0u;                \
            }                                                                      \
    } while (0)

    #pragma unroll
    for (int mi = 0; mi < 2; mi++)
        #pragma unroll
        for (int ni = 0; ni < 4; ni++) { acc16[mi][ni][0] = 0u; acc16[mi][ni][1] = 0u; }

    PC_LOAD(0, 0);

    #pragma unroll 1
    for (int c = 0; c < 16; c++) {
        asm volatile("cp.async.wait_group 0;\n");
        __syncthreads();                          // chunk c resident; buf (c+1)&1 free
        if (c + 1 < 16) PC_LOAD((c + 1) & 1, c + 1);

        const uint32_t base  = smb + (uint32_t)((c & 1) * PC_BUF) * 2;
        const uint32_t baseB = base + (uint32_t)PC_AT * 2;
        #pragma unroll
        for (int kk = 0; kk < 4; kk++) {
            const int ko = kk * 16;
            unsigned bfr[4][2];
            #pragma unroll
            for (int nb = 0; nb < 2; nb++) {
                uint32_t ad = baseB + (uint32_t)((wn * 32 + nb * 16 + bR) * PC_SAS + ko + bK) * 2;
                ldsm4(bfr[2 * nb][0], bfr[2 * nb][1], bfr[2 * nb + 1][0], bfr[2 * nb + 1][1], ad);
            }
            unsigned af[2][4];
            #pragma unroll
            for (int mi = 0; mi < 2; mi++) {
                uint32_t ad = base + (uint32_t)((wm * 32 + mi * 16 + aR) * PC_SAS + ko + aK) * 2;
                ldsm4(af[mi][0], af[mi][1], af[mi][2], af[mi][3], ad);
            }
            #pragma unroll
            for (int mi = 0; mi < 2; mi++)
                #pragma unroll
                for (int ni = 0; ni < 4; ni++)
                    mma16h(acc16[mi][ni], af[mi], bfr[ni]);
            if (kk & 1) PC_PROMOTE();             // promote every K=32 (2 mmas)
        }
    }

    // epilogue: add bias, write Z
    #pragma unroll
    for (int mi = 0; mi < 2; mi++)
        #pragma unroll
        for (int ni = 0; ni < 4; ni++) {
            size_t row = m0 + wm * 32 + mi * 16 + gid;
            int col = n0 + wn * 32 + ni * 8 + 2 * tig;
            float b0 = g_bias[col], b1 = g_bias[col + 1];
            float2 v0 = make_float2(acc[mi][ni][0] + b0, acc[mi][ni][1] + b1);
            float2 v1 = make_float2(acc[mi][ni][2] + b0, acc[mi][ni][3] + b1);
            *reinterpret_cast<float2*>(&g_Z[row * N4 + col])       = v0;
            *reinterpret_cast<float2*>(&g_Z[(row + 8) * N4 + col]) = v1;
        }
}

// ---------------- kernel 3: persistent recurrent LSTM, 512 threads (16 warps) ----------
// 128 CTAs (2 independent mt groups x 64 nt), 64x64 tile, 16 warps 4(M)x4(N),
// warp tile 16x16 (2 ldsm : 4 mma). Wh slice resident in smem; A in 4 chunks of 256.
#define LS_BSAS 1032                            // halfs per resident-B row (1024 + 8 pad)
#define LS_BT   (64 * LS_BSAS)                  // 66048 halfs
#define ST_SAS  136                             // halfs per staging row (128 + 8 pad)
#define ST_BUF  (64 * ST_SAS)                   // 8704 halfs per sub-buffer
#define LS_SMEM ((LS_BT + 4 * ST_BUF) * 2)      // 201728 bytes

__global__ void __launch_bounds__(512) lstm_fp16(float* __restrict__ out) {
    extern __shared__ __half smL[];
    __half* sB = smL;                 // resident Wh slice
    __half* sA = smL + LS_BT;         // 4 staging sub-buffers (2 chunk pairs)

    const int tid = threadIdx.x, lane = tid & 31, wid = tid >> 5;
    const int wm = wid >> 2, wn = wid & 3;       // 4(M) x 4(N)
    const int gid = lane >> 2, tig = lane & 3;
    const int bx = blockIdx.x;
    const int mt = bx >> 6, nt = bx & 63;
    const int m0 = mt * 64, n0 = nt * 64;

    const uint32_t sBb = smem_u32(sB);
    const uint32_t sAb = smem_u32(sA);
    volatile unsigned* barp = (volatile unsigned*)&g_bar2[mt][0];

    const int aR = (lane & 15), aK = ((lane >> 4) << 3);
    const int bR = (lane & 7) + ((lane >> 4) << 3), bK = ((lane >> 3) & 1) << 3;

    // preload resident Wh slice: 64 rows x 1024 halfs = 8192 cp16, 16/thread
    {
        const __half* Wb = g_WhH + (size_t)n0 * 1024;
        #pragma unroll 4
        for (int i = 0; i < 16; i++) {
            int idx = tid + i * 512;
            int r = idx >> 7, s = idx & 127;
            cp16(sB + r * LS_BSAS + s * 8, Wb + (size_t)r * 1024 + s * 8);
        }
        asm volatile("cp.async.commit_group;\n");
        asm volatile("cp.async.wait_group 0;\n");
        __syncthreads();
    }

    float cst[2][2] = {};   // c-state (even-tig lanes): [ni][row/row+8]

    // ---- A chunk loader: 64 rows x 256 halfs = 2048 cp16, 4/thread ----
    #define LOADH(c, hin_) do {                                                     \
        int pr_ = (c) & 1;                                                          \
        __half* d_ = sA + pr_ * 2 * ST_BUF;                                         \
        const __half* sh_ = (hin_) + (size_t)m0 * 1024 + (c) * 256;                 \
        _Pragma("unroll")                                                           \
        for (int i_ = 0; i_ < 4; i_++) { int ix_ = tid + i_ * 512;                  \
            int r_ = ix_ >> 5, s_ = ix_ & 31;                                       \
            cp16(d_ + (s_ >> 4) * ST_BUF + r_ * ST_SAS + (s_ & 15) * 8,             \
                 sh_ + (size_t)r_ * 1024 + s_ * 8); }                               \
        asm volatile("cp.async.commit_group;\n");                                   \
    } while (0)

    for (int t = 0; t < T_SEQ; t++) {
        const __half* hin = g_hH[t & 1];
        __half*      hout = g_hH[(t + 1) & 1];
        const float* Zt   = g_Z + (size_t)t * BATCH * N4;

        // prefetch Z fragments (latency hides under the GEMM)
        float2 z[2][2];
        #pragma unroll
        for (int ni = 0; ni < 2; ni++) {
            int row = m0 + wm * 16 + gid;
            int col = n0 + wn * 16 + ni * 8 + 2 * tig;
            z[ni][0] = *reinterpret_cast<const float2*>(&Zt[(size_t)row * N4 + col]);
            z[ni][1] = *reinterpret_cast<const float2*>(&Zt[(size_t)(row + 8) * N4 + col]);
        }

        float acc[2][4] = {};

        LOADH(0, hin);
        #pragma unroll 1
        for (int c = 0; c < 4; c++) {
            asm volatile("cp.async.wait_group 0;\n");
            __syncthreads();
            if (c + 1 < 4) LOADH(c + 1, hin);
            uint32_t ab = sAb + (uint32_t)((c & 1) * 2 * ST_BUF) * 2;
            #pragma unroll
            for (int kk = 0; kk < 16; kk++) {
                unsigned bfr[2][2];
                ldsm4(bfr[0][0], bfr[0][1], bfr[1][0], bfr[1][1],
                      sBb + (uint32_t)((wn * 16 + bR) * LS_BSAS + c * 256 + kk * 16 + bK) * 2);
                unsigned af[4];
                ldsm4(af[0], af[1], af[2], af[3],
                      ab + (uint32_t)((kk >> 3) * ST_BUF +
                           (wm * 16 + aR) * ST_SAS + (kk & 7) * 16 + aK) * 2);
                #pragma unroll
                for (int ni = 0; ni < 2; ni++)
                    mma16(acc[ni], af, bfr[ni]);
            }
        }

        // elementwise LSTM cell (gate pairs in adjacent lanes; shfl_xor(1) completes quads)
        #pragma unroll
        for (int ni = 0; ni < 2; ni++) {
            int row = m0 + wm * 16 + gid;
            int col = n0 + wn * 16 + ni * 8 + 2 * tig;
            float v0 = acc[ni][0] + z[ni][0].x;
            float v1 = acc[ni][1] + z[ni][0].y;
            float v2 = acc[ni][2] + z[ni][1].x;
            float v3 = acc[ni][3] + z[ni][1].y;
            float p0 = __shfl_xor_sync(0xffffffffu, v0, 1);
            float p1 = __shfl_xor_sync(0xffffffffu, v1, 1);
            float p2 = __shfl_xor_sync(0xffffffffu, v2, 1);
            float p3 = __shfl_xor_sync(0xffffffffu, v3, 1);
            if (!(tig & 1)) {
                int u = col >> 2;
                {
                    float f = sigm(v0), ii = sigm(v1), gg = tanhf(p0), oo = sigm(p1);
                    float cn = cst[ni][0] * f + ii * gg;
                    cst[ni][0] = cn;
                    float h = oo * tanhf(cn);
                    out[(size_t)t * (BATCH * DOUT) + (size_t)row * DOUT + u] = h;
                    hout[row * DOUT + u] = __float2half_rn(h);
                }
                {
                    float f = sigm(v2), ii = sigm(v3), gg = tanhf(p2), oo = sigm(p3);
                    float cn = cst[ni][1] * f + ii * gg;
                    cst[ni][1] = cn;
                    float h = oo * tanhf(cn);
                    out[(size_t)t * (BATCH * DOUT) + (size_t)(row + 8) * DOUT + u] = h;
                    hout[(row + 8) * DOUT + u] = __float2half_rn(h);
                }
            }
        }

        // per-group barrier (64 CTAs): h(t) of this mt group visible before step t+1
        __syncthreads();
        if (tid == 0) {
            __threadfence();
            atomicAdd((unsigned*)barp, 1u);
            unsigned tgt = (unsigned)(t + 1) * (GRID_LSTM / 2);
            while (*barp < tgt) { }
            __threadfence();
        }
        __syncthreads();
    }
}

// ---------------- launch ----------------
extern "C" void kernel_launch(void* const* d_in, const int* in_sizes, int n_in,
                              void* d_out, int out_size) {
    const float* tokens = (const float*)d_in[0];
    const float* Wf = (const float*)d_in[1]; const float* bf = (const float*)d_in[2];
    const float* Wi = (const float*)d_in[3]; const float* bi = (const float*)d_in[4];
    const float* Wc = (const float*)d_in[5]; const float* bc = (const float*)d_in[6];
    const float* Wo = (const float*)d_in[7]; const float* bo = (const float*)d_in[8];

    cudaFuncSetAttribute(precompute_fp16, cudaFuncAttributeMaxDynamicSharedMemorySize, PC_SMEM);
    cudaFuncSetAttribute(lstm_fp16,       cudaFuncAttributeMaxDynamicSharedMemorySize, LS_SMEM);

    pack_kernel<<<2048, 256>>>(tokens, Wf, bf, Wi, bi, Wc, bc, Wo, bo);
    precompute_fp16<<<512 * 64, 256, PC_SMEM>>>();
    lstm_fp16<<<GRID_LSTM, 512, LS_SMEM>>>((float*)d_out);
}

// round 12
// speedup vs baseline: 1.1419x; 1.1419x over previous
#include <cuda_runtime.h>
#include <cuda_fp16.h>
#include <cstdint>
#include <cstddef>

#define T_SEQ 512
#define BATCH 128
#define DIN   1024
#define DOUT  1024
#define N4    4096          // 4 gates * DOUT, gate-interleaved: n = unit*4 + gate
#define GRID_LSTM 128

// ---------------- static device scratch (no allocations allowed) ----------------
__device__ __align__(256) __half g_ZH  [(size_t)T_SEQ * BATCH * N4]; // 512 MiB fp16 preactivations (x-part + bias)
__device__ __align__(256) __half g_WxH [(size_t)N4 * DIN];           // packed fp16 x-weights
__device__ __align__(256) __half g_WhH [(size_t)N4 * DOUT];          // packed fp16 h-weights
__device__ __align__(256) float  g_bias[N4];
__device__ __align__(256) __half g_XhH [(size_t)T_SEQ * BATCH * DIN];// fp16 tokens
__device__ __align__(256) __half g_hH  [2][BATCH * DOUT];            // ping-pong hidden state fp16
__device__ unsigned g_bar2[2][32];                                   // per-mt-group barrier counters

// ---------------- helpers ----------------
__device__ __forceinline__ void cp16(void* smem_dst, const void* gsrc) {
    unsigned s = (unsigned)__cvta_generic_to_shared(smem_dst);
    asm volatile("cp.async.cg.shared.global [%0], [%1], 16;\n" :: "r"(s), "l"(gsrc));
}

__device__ __forceinline__ void ldsm4(unsigned& r0, unsigned& r1, unsigned& r2, unsigned& r3,
                                      uint32_t addr) {
    asm volatile("ldmatrix.sync.aligned.m8n8.x4.shared.b16 {%0,%1,%2,%3}, [%4];"
                 : "=r"(r0), "=r"(r1), "=r"(r2), "=r"(r3) : "r"(addr));
}

__device__ __forceinline__ void mma16(float* d, const unsigned* a, const unsigned* b) {
    asm volatile(
        "mma.sync.aligned.m16n8k16.row.col.f32.f16.f16.f32 "
        "{%0,%1,%2,%3}, {%4,%5,%6,%7}, {%8,%9}, {%0,%1,%2,%3};\n"
        : "+f"(d[0]), "+f"(d[1]), "+f"(d[2]), "+f"(d[3])
        : "r"(a[0]), "r"(a[1]), "r"(a[2]), "r"(a[3]), "r"(b[0]), "r"(b[1]));
}

__device__ __forceinline__ float sigm(float x) { return 1.f / (1.f + __expf(-x)); }

__device__ __forceinline__ uint32_t smem_u32(const void* p) {
    return (uint32_t)__cvta_generic_to_shared(p);
}

// ---------------- kernel 1: pack weights / convert tokens / reset state ----------------
__global__ void __launch_bounds__(256) pack_kernel(
    const float* __restrict__ tokens,
    const float* __restrict__ Wf, const float* __restrict__ bf,
    const float* __restrict__ Wi, const float* __restrict__ bi,
    const float* __restrict__ Wc, const float* __restrict__ bc,
    const float* __restrict__ Wo, const float* __restrict__ bo)
{
    size_t tid = (size_t)blockIdx.x * blockDim.x + threadIdx.x;
    size_t nth = (size_t)gridDim.x * blockDim.x;
    if (tid < 64) g_bar2[tid >> 5][tid & 31] = 0;   // reset barriers every launch (graph replays)

    for (size_t i = tid; i < (size_t)N4 * 1024; i += nth) {
        int n = (int)(i >> 10), k = (int)(i & 1023);
        int u = n >> 2, g = n & 3;
        const float* W = (g == 0) ? Wf : (g == 1) ? Wi : (g == 2) ? Wc : Wo;
        g_WxH[i] = __float2half_rn(W[(size_t)u * 2048 + k]);
        g_WhH[i] = __float2half_rn(W[(size_t)u * 2048 + 1024 + k]);
    }
    for (size_t i = tid; i < (size_t)N4; i += nth) {
        int u = (int)(i >> 2), g = (int)(i & 3);
        const float* bb = (g == 0) ? bf : (g == 1) ? bi : (g == 2) ? bc : bo;
        g_bias[i] = bb[u];
    }
    for (size_t i = tid; i < (size_t)T_SEQ * BATCH * DIN; i += nth)
        g_XhH[i] = __float2half_rn(tokens[i]);
    for (size_t i = tid; i < (size_t)BATCH * DOUT; i += nth)
        g_hH[0][i] = __float2half_rn(0.f);   // h0 = 0
}

// ---------------- kernel 2: fp16 mma (f32 acc): Z = X @ Wx^T + b -> fp16 ----------------
// CTA tile 128x128, 256 threads = 8 warps 2(M)x4(N); warp tile 64x32; K-chunk 64.
// 2 CTAs/SM -> 16 warps/SM. (R10 config — measured at the legacy-HMMA pipe ceiling.)
#define PC_SAS  72                    // halfs per smem row (64 data + 8 pad)
#define PC_PT   (128 * PC_SAS)        // halfs per 128x64 tile (9216)
#define PC_SMEM (2 * 2 * PC_PT * 2)   // bytes = 73728 (A,B x double buffer)

__global__ void __launch_bounds__(256, 2) precompute_fp16() {
    extern __shared__ __half smH[];
    const int tid = threadIdx.x, lane = tid & 31, wid = tid >> 5;
    const int wm = wid >> 2, wn = wid & 3;
    const int gid = lane >> 2, tig = lane & 3;
    const int bx = blockIdx.x;
    const int mt = bx >> 5, nt = bx & 31;        // nt fastest: A tile shared in L2
    const size_t m0 = (size_t)mt * 128;
    const int n0 = nt * 128;

    const __half* Ax = g_XhH + m0 * 1024;
    const __half* Bw = g_WxH + (size_t)n0 * 1024;
    const uint32_t smb = smem_u32(smH);

    const int aR = (lane & 15), aK = ((lane >> 4) << 3);
    const int bR = (lane & 7) + ((lane >> 4) << 3), bK = ((lane >> 3) & 1) << 3;

    float acc[4][4][4] = {};

    #define PC_LOAD(buf, c) do {                                                   \
        __half* d_ = smH + (buf) * 2 * PC_PT;                                      \
        int k0_ = (c) * 64;                                                        \
        _Pragma("unroll")                                                          \
        for (int i_ = 0; i_ < 4; i_++) { int ix_ = tid + i_ * 256;                 \
            int r_ = ix_ >> 3, s_ = ix_ & 7;                                       \
            cp16(d_ + r_ * PC_SAS + s_ * 8, Ax + (size_t)r_ * 1024 + k0_ + s_ * 8);} \
        _Pragma("unroll")                                                          \
        for (int i_ = 0; i_ < 4; i_++) { int ix_ = tid + i_ * 256;                 \
            int r_ = ix_ >> 3, s_ = ix_ & 7;                                       \
            cp16(d_ + PC_PT + r_ * PC_SAS + s_ * 8, Bw + (size_t)r_ * 1024 + k0_ + s_ * 8);} \
        asm volatile("cp.async.commit_group;\n");                                  \
    } while (0)

    PC_LOAD(0, 0);

    #pragma unroll 1
    for (int c = 0; c < 16; c++) {
        asm volatile("cp.async.wait_group 0;\n");
        __syncthreads();
        if (c + 1 < 16) PC_LOAD((c + 1) & 1, c + 1);

        const uint32_t base = smb + (uint32_t)((c & 1) * 2 * PC_PT) * 2;
        #pragma unroll
        for (int kk = 0; kk < 4; kk++) {
            const int ko = kk * 16;
            unsigned bfr[4][2];
            #pragma unroll
            for (int nb = 0; nb < 2; nb++) {
                uint32_t ad = base + (uint32_t)PC_PT * 2 +
                              (uint32_t)((wn * 32 + nb * 16 + bR) * PC_SAS + ko + bK) * 2;
                ldsm4(bfr[2 * nb][0], bfr[2 * nb][1], bfr[2 * nb + 1][0], bfr[2 * nb + 1][1], ad);
            }
            unsigned af[4][4];
            #pragma unroll
            for (int mi = 0; mi < 4; mi++) {
                uint32_t ad = base + (uint32_t)((wm * 64 + mi * 16 + aR) * PC_SAS + ko + aK) * 2;
                ldsm4(af[mi][0], af[mi][1], af[mi][2], af[mi][3], ad);
            }
            #pragma unroll
            for (int mi = 0; mi < 4; mi++)
                #pragma unroll
                for (int ni = 0; ni < 4; ni++)
                    mma16(acc[mi][ni], af[mi], bfr[ni]);
        }
    }

    // epilogue: add bias, write Z as fp16 (half2 stores)
    #pragma unroll
    for (int mi = 0; mi < 4; mi++)
        #pragma unroll
        for (int ni = 0; ni < 4; ni++) {
            size_t row = m0 + wm * 64 + mi * 16 + gid;
            int col = n0 + wn * 32 + ni * 8 + 2 * tig;
            float b0 = g_bias[col], b1 = g_bias[col + 1];
            *reinterpret_cast<__half2*>(&g_ZH[row * N4 + col]) =
                __floats2half2_rn(acc[mi][ni][0] + b0, acc[mi][ni][1] + b1);
            *reinterpret_cast<__half2*>(&g_ZH[(row + 8) * N4 + col]) =
                __floats2half2_rn(acc[mi][ni][2] + b0, acc[mi][ni][3] + b1);
        }
}

// ---------------- kernel 3: persistent recurrent LSTM, 512 threads (16 warps) ----------
// 128 CTAs (2 independent mt groups x 64 nt), 64x64 tile, 16 warps 4(M)x4(N),
// warp tile 16x16. Wh resident in smem; A in 4 chunks of 256 (2 issued up-front).
// Epilogue staged in smem -> coalesced 16B stores; balanced even/odd-lane cell math.
#define LS_BSAS 1032                            // halfs per resident-B row (1024 + 8 pad)
#define LS_BT   (64 * LS_BSAS)                  // 66048 halfs
#define ST_SAS  136                             // halfs per staging row (128 + 8 pad)
#define ST_BUF  (64 * ST_SAS)                   // 8704 halfs per sub-buffer
#define LS_SMEM ((LS_BT + 4 * ST_BUF) * 2)      // 201728 bytes

__global__ void __launch_bounds__(512) lstm_fp16(float* __restrict__ out) {
    extern __shared__ __half smL[];
    __half* sB = smL;                 // resident Wh slice
    __half* sA = smL + LS_BT;         // 4 staging sub-buffers (2 chunk pairs)
    float*  sOF = reinterpret_cast<float*>(sA);   // out-tile staging: 64 x 16 f32, stride 20
    __half* sOH = sA + 2560;                      // h-tile staging: 64 x 16 f16, stride 24

    const int tid = threadIdx.x, lane = tid & 31, wid = tid >> 5;
    const int wm = wid >> 2, wn = wid & 3;       // 4(M) x 4(N)
    const int gid = lane >> 2, tig = lane & 3;
    const int bx = blockIdx.x;
    const int mt = bx >> 6, nt = bx & 63;
    const int m0 = mt * 64, n0 = nt * 64;

    const uint32_t sBb = smem_u32(sB);
    const uint32_t sAb = smem_u32(sA);
    volatile unsigned* barp = (volatile unsigned*)&g_bar2[mt][0];

    const int aR = (lane & 15), aK = ((lane >> 4) << 3);
    const int bR = (lane & 7) + ((lane >> 4) << 3), bK = ((lane >> 3) & 1) << 3;

    // preload resident Wh slice: 64 rows x 1024 halfs = 8192 cp16, 16/thread
    {
        const __half* Wb = g_WhH + (size_t)n0 * 1024;
        #pragma unroll 4
        for (int i = 0; i < 16; i++) {
            int idx = tid + i * 512;
            int r = idx >> 7, s = idx & 127;
            cp16(sB + r * LS_BSAS + s * 8, Wb + (size_t)r * 1024 + s * 8);
        }
        asm volatile("cp.async.commit_group;\n");
        asm volatile("cp.async.wait_group 0;\n");
        __syncthreads();
    }

    // c-state: even lanes hold row gid, odd lanes row gid+8; [ni]
    float cst[2] = {0.f, 0.f};
    const int odd = tig & 1;
    const int row_l = wm * 16 + gid + (odd ? 8 : 0);

    // ---- A chunk loader: 64 rows x 256 halfs = 2048 cp16, 4/thread ----
    #define LOADH(c, hin_) do {                                                     \
        int pr_ = (c) & 1;                                                          \
        __half* d_ = sA + pr_ * 2 * ST_BUF;                                         \
        const __half* sh_ = (hin_) + (size_t)m0 * 1024 + (c) * 256;                 \
        _Pragma("unroll")                                                           \
        for (int i_ = 0; i_ < 4; i_++) { int ix_ = tid + i_ * 512;                  \
            int r_ = ix_ >> 5, s_ = ix_ & 31;                                       \
            cp16(d_ + (s_ >> 4) * ST_BUF + r_ * ST_SAS + (s_ & 15) * 8,             \
                 sh_ + (size_t)r_ * 1024 + s_ * 8); }                               \
        asm volatile("cp.async.commit_group;\n");                                   \
    } while (0)

    for (int t = 0; t < T_SEQ; t++) {
        const __half* hin = g_hH[t & 1];
        __half*      hout = g_hH[(t + 1) & 1];
        const __half* ZtH = g_ZH + (size_t)t * BATCH * N4;

        // issue first two A chunks immediately
        LOADH(0, hin);
        LOADH(1, hin);

        // prefetch Z fragments (fp16; latency hides under the GEMM)
        unsigned zr[2][2];
        #pragma unroll
        for (int ni = 0; ni < 2; ni++) {
            int row = m0 + wm * 16 + gid;
            int col = n0 + wn * 16 + ni * 8 + 2 * tig;
            zr[ni][0] = *reinterpret_cast<const unsigned*>(&ZtH[(size_t)row * N4 + col]);
            zr[ni][1] = *reinterpret_cast<const unsigned*>(&ZtH[(size_t)(row + 8) * N4 + col]);
        }

        float acc[2][4] = {};

        #pragma unroll 1
        for (int c = 0; c < 4; c++) {
            if (c == 0) asm volatile("cp.async.wait_group 1;\n");
            else        asm volatile("cp.async.wait_group 0;\n");
            __syncthreads();
            if (c >= 1 && c + 1 < 4) LOADH(c + 1, hin);
            uint32_t ab = sAb + (uint32_t)((c & 1) * 2 * ST_BUF) * 2;
            #pragma unroll
            for (int kk = 0; kk < 16; kk++) {
                unsigned bfr[2][2];
                ldsm4(bfr[0][0], bfr[0][1], bfr[1][0], bfr[1][1],
                      sBb + (uint32_t)((wn * 16 + bR) * LS_BSAS + c * 256 + kk * 16 + bK) * 2);
                unsigned af[4];
                ldsm4(af[0], af[1], af[2], af[3],
                      ab + (uint32_t)((kk >> 3) * ST_BUF +
                           (wm * 16 + aR) * ST_SAS + (kk & 7) * 16 + aK) * 2);
                #pragma unroll
                for (int ni = 0; ni < 2; ni++)
                    mma16(acc[ni], af, bfr[ni]);
            }
        }

        // elementwise: add Z, swap with lane^1; even lane -> row gid, odd -> row gid+8
        float hres[2];
        #pragma unroll
        for (int ni = 0; ni < 2; ni++) {
            float2 z0 = __half22float2(*reinterpret_cast<__half2*>(&zr[ni][0]));
            float2 z1 = __half22float2(*reinterpret_cast<__half2*>(&zr[ni][1]));
            float v0 = acc[ni][0] + z0.x;
            float v1 = acc[ni][1] + z0.y;
            float v2 = acc[ni][2] + z1.x;
            float v3 = acc[ni][3] + z1.y;
            float p0 = __shfl_xor_sync(0xffffffffu, v0, 1);
            float p1 = __shfl_xor_sync(0xffffffffu, v1, 1);
            float p2 = __shfl_xor_sync(0xffffffffu, v2, 1);
            float p3 = __shfl_xor_sync(0xffffffffu, v3, 1);
            // even lane: f,i = v0,v1 (own), g,o = p0,p1 (partner)   -> row gid
            // odd  lane: f,i = p2,p3 (partner), g,o = v2,v3 (own)   -> row gid+8
            float gf = odd ? p2 : v0;
            float gi = odd ? p3 : v1;
            float gg = odd ? v2 : p0;
            float go = odd ? v3 : p1;
            float f = sigm(gf), ii = sigm(gi), g = tanhf(gg), o = sigm(go);
            float cn = cst[ni] * f + ii * g;
            cst[ni] = cn;
            hres[ni] = o * tanhf(cn);
        }

        __syncthreads();   // all ldsm reads of sA done -> safe to reuse as staging

        #pragma unroll
        for (int ni = 0; ni < 2; ni++) {
            int u_l = wn * 4 + ni * 2 + (tig >> 1);
            sOF[row_l * 20 + u_l] = hres[ni];
            sOH[row_l * 24 + u_l] = __float2half_rn(hres[ni]);
        }

        __syncthreads();

        // coalesced stores: out-tile 64x16 f32, h-tile 64x16 f16
        if (tid < 256) {
            int r = tid >> 2, j = tid & 3;
            float4 v = *reinterpret_cast<float4*>(&sOF[r * 20 + j * 4]);
            *reinterpret_cast<float4*>(
                &out[(size_t)t * (BATCH * DOUT) + (size_t)(m0 + r) * DOUT + nt * 16 + j * 4]) = v;
        } else if (tid < 384) {
            int k = tid - 256, r = k >> 1, p = k & 1;
            uint4 v = *reinterpret_cast<uint4*>(&sOH[r * 24 + p * 8]);
            *reinterpret_cast<uint4*>(&hout[(size_t)(m0 + r) * DOUT + nt * 16 + p * 8]) = v;
        }

        // per-group barrier (64 CTAs)
        __syncthreads();
        if (tid == 0) {
            __threadfence();
            atomicAdd((unsigned*)barp, 1u);
            unsigned tgt = (unsigned)(t + 1) * (GRID_LSTM / 2);
            while (*barp < tgt) { }
            __threadfence();
        }
        __syncthreads();
    }
}

// ---------------- launch ----------------
extern "C" void kernel_launch(void* const* d_in, const int* in_sizes, int n_in,
                              void* d_out, int out_size) {
    const float* tokens = (const float*)d_in[0];
    const float* Wf = (const float*)d_in[1]; const float* bf = (const float*)d_in[2];
    const float* Wi = (const float*)d_in[3]; const float* bi = (const float*)d_in[4];
    const float* Wc = (const float*)d_in[5]; const float* bc = (const float*)d_in[6];
    const float* Wo = (const float*)d_in[7]; const float* bo = (const float*)d_in[8];

    cudaFuncSetAttribute(precompute_fp16, cudaFuncAttributeMaxDynamicSharedMemorySize, PC_SMEM);
    cudaFuncSetAttribute(lstm_fp16,       cudaFuncAttributeMaxDynamicSharedMemorySize, LS_SMEM);

    pack_kernel<<<2048, 256>>>(tokens, Wf, bf, Wi, bi, Wc, bc, Wo, bo);
    precompute_fp16<<<512 * 32, 256, PC_SMEM>>>();
    lstm_fp16<<<GRID_LSTM, 512, LS_SMEM>>>((float*)d_out);
}

// round 13
// speedup vs baseline: 1.1426x; 1.0006x over previous
#include <cuda_runtime.h>
#include <cuda_fp16.h>
#include <cstdint>
#include <cstddef>

#define T_SEQ 512
#define BATCH 128
#define DIN   1024
#define DOUT  1024
#define N4    4096          // 4 gates * DOUT, gate-interleaved: n = unit*4 + gate
#define GRID_LSTM 128

// ---------------- static device scratch (no allocations allowed) ----------------
__device__ __align__(256) __half g_ZH  [(size_t)T_SEQ * BATCH * N4]; // 512 MiB fp16 preactivations (x-part + bias)
__device__ __align__(256) __half g_WxH [(size_t)N4 * DIN];           // packed fp16 x-weights
__device__ __align__(256) __half g_WhH [(size_t)N4 * DOUT];          // packed fp16 h-weights
__device__ __align__(256) float  g_bias[N4];
__device__ __align__(256) __half g_XhH [(size_t)T_SEQ * BATCH * DIN];// fp16 tokens
__device__ __align__(256) __half g_hH  [2][BATCH * DOUT];            // ping-pong hidden state fp16
__device__ unsigned g_bar2[2][32];                                   // per-mt-group barrier counters

// ---------------- helpers ----------------
__device__ __forceinline__ void cp16(void* smem_dst, const void* gsrc) {
    unsigned s = (unsigned)__cvta_generic_to_shared(smem_dst);
    asm volatile("cp.async.cg.shared.global [%0], [%1], 16;\n" :: "r"(s), "l"(gsrc));
}

__device__ __forceinline__ void ldsm4(unsigned& r0, unsigned& r1, unsigned& r2, unsigned& r3,
                                      uint32_t addr) {
    asm volatile("ldmatrix.sync.aligned.m8n8.x4.shared.b16 {%0,%1,%2,%3}, [%4];"
                 : "=r"(r0), "=r"(r1), "=r"(r2), "=r"(r3) : "r"(addr));
}

__device__ __forceinline__ void mma16(float* d, const unsigned* a, const unsigned* b) {
    asm volatile(
        "mma.sync.aligned.m16n8k16.row.col.f32.f16.f16.f32 "
        "{%0,%1,%2,%3}, {%4,%5,%6,%7}, {%8,%9}, {%0,%1,%2,%3};\n"
        : "+f"(d[0]), "+f"(d[1]), "+f"(d[2]), "+f"(d[3])
        : "r"(a[0]), "r"(a[1]), "r"(a[2]), "r"(a[3]), "r"(b[0]), "r"(b[1]));
}

__device__ __forceinline__ float sigm(float x) { return 1.f / (1.f + __expf(-x)); }

__device__ __forceinline__ uint32_t smem_u32(const void* p) {
    return (uint32_t)__cvta_generic_to_shared(p);
}

// ---------------- kernel 1: pack weights / convert tokens / reset state ----------------
__global__ void __launch_bounds__(256) pack_kernel(
    const float* __restrict__ tokens,
    const float* __restrict__ Wf, const float* __restrict__ bf,
    const float* __restrict__ Wi, const float* __restrict__ bi,
    const float* __restrict__ Wc, const float* __restrict__ bc,
    const float* __restrict__ Wo, const float* __restrict__ bo)
{
    size_t tid = (size_t)blockIdx.x * blockDim.x + threadIdx.x;
    size_t nth = (size_t)gridDim.x * blockDim.x;
    if (tid < 64) g_bar2[tid >> 5][tid & 31] = 0;   // reset barriers every launch (graph replays)

    for (size_t i = tid; i < (size_t)N4 * 1024; i += nth) {
        int n = (int)(i >> 10), k = (int)(i & 1023);
        int u = n >> 2, g = n & 3;
        const float* W = (g == 0) ? Wf : (g == 1) ? Wi : (g == 2) ? Wc : Wo;
        g_WxH[i] = __float2half_rn(W[(size_t)u * 2048 + k]);
        g_WhH[i] = __float2half_rn(W[(size_t)u * 2048 + 1024 + k]);
    }
    for (size_t i = tid; i < (size_t)N4; i += nth) {
        int u = (int)(i >> 2), g = (int)(i & 3);
        const float* bb = (g == 0) ? bf : (g == 1) ? bi : (g == 2) ? bc : bo;
        g_bias[i] = bb[u];
    }
    for (size_t i = tid; i < (size_t)T_SEQ * BATCH * DIN; i += nth)
        g_XhH[i] = __float2half_rn(tokens[i]);
    for (size_t i = tid; i < (size_t)BATCH * DOUT; i += nth)
        g_hH[0][i] = __float2half_rn(0.f);   // h0 = 0
}

// ---------------- kernel 2: fp16 mma (f32 acc): Z = X @ Wx^T + b -> fp16 ----------------
// CTA tile 128x128, 256 threads = 8 warps 2(M)x4(N); warp tile 64x32; K-chunk 64.
// 2 CTAs/SM -> 16 warps/SM. (Measured at the legacy-HMMA pipe ceiling.)
#define PC_SAS  72                    // halfs per smem row (64 data + 8 pad)
#define PC_PT   (128 * PC_SAS)        // halfs per 128x64 tile (9216)
#define PC_SMEM (2 * 2 * PC_PT * 2)   // bytes = 73728 (A,B x double buffer)

__global__ void __launch_bounds__(256, 2) precompute_fp16() {
    extern __shared__ __half smH[];
    const int tid = threadIdx.x, lane = tid & 31, wid = tid >> 5;
    const int wm = wid >> 2, wn = wid & 3;
    const int gid = lane >> 2, tig = lane & 3;
    const int bx = blockIdx.x;
    const int mt = bx >> 5, nt = bx & 31;        // nt fastest: A tile shared in L2
    const size_t m0 = (size_t)mt * 128;
    const int n0 = nt * 128;

    const __half* Ax = g_XhH + m0 * 1024;
    const __half* Bw = g_WxH + (size_t)n0 * 1024;
    const uint32_t smb = smem_u32(smH);

    const int aR = (lane & 15), aK = ((lane >> 4) << 3);
    const int bR = (lane & 7) + ((lane >> 4) << 3), bK = ((lane >> 3) & 1) << 3;

    float acc[4][4][4] = {};

    #define PC_LOAD(buf, c) do {                                                   \
        __half* d_ = smH + (buf) * 2 * PC_PT;                                      \
        int k0_ = (c) * 64;                                                        \
        _Pragma("unroll")                                                          \
        for (int i_ = 0; i_ < 4; i_++) { int ix_ = tid + i_ * 256;                 \
            int r_ = ix_ >> 3, s_ = ix_ & 7;                                       \
            cp16(d_ + r_ * PC_SAS + s_ * 8, Ax + (size_t)r_ * 1024 + k0_ + s_ * 8);} \
        _Pragma("unroll")                                                          \
        for (int i_ = 0; i_ < 4; i_++) { int ix_ = tid + i_ * 256;                 \
            int r_ = ix_ >> 3, s_ = ix_ & 7;                                       \
            cp16(d_ + PC_PT + r_ * PC_SAS + s_ * 8, Bw + (size_t)r_ * 1024 + k0_ + s_ * 8);} \
        asm volatile("cp.async.commit_group;\n");                                  \
    } while (0)

    PC_LOAD(0, 0);

    #pragma unroll 1
    for (int c = 0; c < 16; c++) {
        asm volatile("cp.async.wait_group 0;\n");
        __syncthreads();
        if (c + 1 < 16) PC_LOAD((c + 1) & 1, c + 1);

        const uint32_t base = smb + (uint32_t)((c & 1) * 2 * PC_PT) * 2;
        #pragma unroll
        for (int kk = 0; kk < 4; kk++) {
            const int ko = kk * 16;
            unsigned bfr[4][2];
            #pragma unroll
            for (int nb = 0; nb < 2; nb++) {
                uint32_t ad = base + (uint32_t)PC_PT * 2 +
                              (uint32_t)((wn * 32 + nb * 16 + bR) * PC_SAS + ko + bK) * 2;
                ldsm4(bfr[2 * nb][0], bfr[2 * nb][1], bfr[2 * nb + 1][0], bfr[2 * nb + 1][1], ad);
            }
            unsigned af[4][4];
            #pragma unroll
            for (int mi = 0; mi < 4; mi++) {
                uint32_t ad = base + (uint32_t)((wm * 64 + mi * 16 + aR) * PC_SAS + ko + aK) * 2;
                ldsm4(af[mi][0], af[mi][1], af[mi][2], af[mi][3], ad);
            }
            #pragma unroll
            for (int mi = 0; mi < 4; mi++)
                #pragma unroll
                for (int ni = 0; ni < 4; ni++)
                    mma16(acc[mi][ni], af[mi], bfr[ni]);
        }
    }

    // epilogue: add bias, write Z as fp16 (half2 stores)
    #pragma unroll
    for (int mi = 0; mi < 4; mi++)
        #pragma unroll
        for (int ni = 0; ni < 4; ni++) {
            size_t row = m0 + wm * 64 + mi * 16 + gid;
            int col = n0 + wn * 32 + ni * 8 + 2 * tig;
            float b0 = g_bias[col], b1 = g_bias[col + 1];
            *reinterpret_cast<__half2*>(&g_ZH[row * N4 + col]) =
                __floats2half2_rn(acc[mi][ni][0] + b0, acc[mi][ni][1] + b1);
            *reinterpret_cast<__half2*>(&g_ZH[(row + 8) * N4 + col]) =
                __floats2half2_rn(acc[mi][ni][2] + b0, acc[mi][ni][3] + b1);
        }
}

// ---------------- kernel 3: persistent recurrent LSTM, 512 threads (16 warps) ----------
// 128 CTAs (2 independent mt groups x 64 nt), 64x64 tile, 16 warps 4(M)x4(N),
// warp tile 16x16. Wh resident in smem; A in 4 chunks of 256.
// Tail: hout store + barrier ARRIVE first; fp32 out store + spin in barrier shadow.
#define LS_BSAS 1032                            // halfs per resident-B row (1024 + 8 pad)
#define LS_BT   (64 * LS_BSAS)                  // 66048 halfs
#define ST_SAS  136                             // halfs per staging row (128 + 8 pad)
#define ST_BUF  (64 * ST_SAS)                   // 8704 halfs per sub-buffer
#define LS_SMEM ((LS_BT + 4 * ST_BUF) * 2)      // 201728 bytes

__global__ void __launch_bounds__(512) lstm_fp16(float* __restrict__ out) {
    extern __shared__ __half smL[];
    __half* sB = smL;                 // resident Wh slice
    __half* sA = smL + LS_BT;         // 4 staging sub-buffers (2 chunk pairs)
    float*  sOF = reinterpret_cast<float*>(sA);   // out-tile staging: 64 x 16 f32, stride 20 (bytes [0,5120))
    __half* sOH = sA + 2560;                      // h-tile staging: 64 x 16 f16, stride 24 (bytes [5120,8192))

    const int tid = threadIdx.x, lane = tid & 31, wid = tid >> 5;
    const int wm = wid >> 2, wn = wid & 3;       // 4(M) x 4(N)
    const int gid = lane >> 2, tig = lane & 3;
    const int bx = blockIdx.x;
    const int mt = bx >> 6, nt = bx & 63;
    const int m0 = mt * 64, n0 = nt * 64;

    const uint32_t sBb = smem_u32(sB);
    const uint32_t sAb = smem_u32(sA);
    volatile unsigned* barp = (volatile unsigned*)&g_bar2[mt][0];

    const int aR = (lane & 15), aK = ((lane >> 4) << 3);
    const int bR = (lane & 7) + ((lane >> 4) << 3), bK = ((lane >> 3) & 1) << 3;

    // preload resident Wh slice: 64 rows x 1024 halfs = 8192 cp16, 16/thread
    {
        const __half* Wb = g_WhH + (size_t)n0 * 1024;
        #pragma unroll 4
        for (int i = 0; i < 16; i++) {
            int idx = tid + i * 512;
            int r = idx >> 7, s = idx & 127;
            cp16(sB + r * LS_BSAS + s * 8, Wb + (size_t)r * 1024 + s * 8);
        }
        asm volatile("cp.async.commit_group;\n");
        asm volatile("cp.async.wait_group 0;\n");
        __syncthreads();
    }

    // c-state: even lanes hold row gid, odd lanes row gid+8; [ni]
    float cst[2] = {0.f, 0.f};
    const int odd = tig & 1;
    const int row_l = wm * 16 + gid + (odd ? 8 : 0);

    // ---- A chunk loader: 64 rows x 256 halfs = 2048 cp16, 4/thread ----
    #define LOADH(c, hin_) do {                                                     \
        int pr_ = (c) & 1;                                                          \
        __half* d_ = sA + pr_ * 2 * ST_BUF;                                         \
        const __half* sh_ = (hin_) + (size_t)m0 * 1024 + (c) * 256;                 \
        _Pragma("unroll")                                                           \
        for (int i_ = 0; i_ < 4; i_++) { int ix_ = tid + i_ * 512;                  \
            int r_ = ix_ >> 5, s_ = ix_ & 31;                                       \
            cp16(d_ + (s_ >> 4) * ST_BUF + r_ * ST_SAS + (s_ & 15) * 8,             \
                 sh_ + (size_t)r_ * 1024 + s_ * 8); }                               \
        asm volatile("cp.async.commit_group;\n");                                   \
    } while (0)

    for (int t = 0; t < T_SEQ; t++) {
        const __half* hin = g_hH[t & 1];
        __half*      hout = g_hH[(t + 1) & 1];
        const __half* ZtH = g_ZH + (size_t)t * BATCH * N4;

        // issue first two A chunks immediately
        LOADH(0, hin);
        LOADH(1, hin);

        // prefetch Z fragments (fp16, streaming; latency hides under the GEMM)
        unsigned zr[2][2];
        #pragma unroll
        for (int ni = 0; ni < 2; ni++) {
            int row = m0 + wm * 16 + gid;
            int col = n0 + wn * 16 + ni * 8 + 2 * tig;
            zr[ni][0] = __ldcs(reinterpret_cast<const unsigned*>(&ZtH[(size_t)row * N4 + col]));
            zr[ni][1] = __ldcs(reinterpret_cast<const unsigned*>(&ZtH[(size_t)(row + 8) * N4 + col]));
        }

        float acc[2][4] = {};

        #pragma unroll 1
        for (int c = 0; c < 4; c++) {
            if (c == 0) asm volatile("cp.async.wait_group 1;\n");
            else        asm volatile("cp.async.wait_group 0;\n");
            __syncthreads();
            if (c >= 1 && c + 1 < 4) LOADH(c + 1, hin);
            uint32_t ab = sAb + (uint32_t)((c & 1) * 2 * ST_BUF) * 2;
            #pragma unroll
            for (int kk = 0; kk < 16; kk++) {
                unsigned bfr[2][2];
                ldsm4(bfr[0][0], bfr[0][1], bfr[1][0], bfr[1][1],
                      sBb + (uint32_t)((wn * 16 + bR) * LS_BSAS + c * 256 + kk * 16 + bK) * 2);
                unsigned af[4];
                ldsm4(af[0], af[1], af[2], af[3],
                      ab + (uint32_t)((kk >> 3) * ST_BUF +
                           (wm * 16 + aR) * ST_SAS + (kk & 7) * 16 + aK) * 2);
                #pragma unroll
                for (int ni = 0; ni < 2; ni++)
                    mma16(acc[ni], af, bfr[ni]);
            }
        }

        // elementwise: add Z, swap with lane^1; even lane -> row gid, odd -> row gid+8
        float hres[2];
        #pragma unroll
        for (int ni = 0; ni < 2; ni++) {
            float2 z0 = __half22float2(*reinterpret_cast<__half2*>(&zr[ni][0]));
            float2 z1 = __half22float2(*reinterpret_cast<__half2*>(&zr[ni][1]));
            float v0 = acc[ni][0] + z0.x;
            float v1 = acc[ni][1] + z0.y;
            float v2 = acc[ni][2] + z1.x;
            float v3 = acc[ni][3] + z1.y;
            float p0 = __shfl_xor_sync(0xffffffffu, v0, 1);
            float p1 = __shfl_xor_sync(0xffffffffu, v1, 1);
            float p2 = __shfl_xor_sync(0xffffffffu, v2, 1);
            float p3 = __shfl_xor_sync(0xffffffffu, v3, 1);
            float gf = odd ? p2 : v0;
            float gi = odd ? p3 : v1;
            float gg = odd ? v2 : p0;
            float go = odd ? v3 : p1;
            float f = sigm(gf), ii = sigm(gi), g = tanhf(gg), o = sigm(go);
            float cn = cst[ni] * f + ii * g;
            cst[ni] = cn;
            hres[ni] = o * tanhf(cn);
        }

        __syncthreads();   // all ldsm reads of sA done -> staging regions reusable

        // ---- phase 1: h (fp16) staging + store + barrier ARRIVE (critical path) ----
        #pragma unroll
        for (int ni = 0; ni < 2; ni++) {
            int u_l = wn * 4 + ni * 2 + (tig >> 1);
            sOH[row_l * 24 + u_l] = __float2half_rn(hres[ni]);
        }
        __syncthreads();
        if (tid >= 256 && tid < 384) {
            int k = tid - 256, r = k >> 1, p = k & 1;
            uint4 v = *reinterpret_cast<uint4*>(&sOH[r * 24 + p * 8]);
            *reinterpret_cast<uint4*>(&hout[(size_t)(m0 + r) * DOUT + nt * 16 + p * 8]) = v;
        }
        __syncthreads();
        const bool last = (t + 1 == T_SEQ);
        if (tid == 0 && !last) {
            __threadfence();
            atomicAdd((unsigned*)barp, 1u);
        }

        // ---- phase 2: fp32 out staging + store in the barrier shadow ----
        #pragma unroll
        for (int ni = 0; ni < 2; ni++) {
            int u_l = wn * 4 + ni * 2 + (tig >> 1);
            sOF[row_l * 20 + u_l] = hres[ni];
        }
        __syncthreads();
        if (tid < 256) {
            int r = tid >> 2, j = tid & 3;
            float4 v = *reinterpret_cast<float4*>(&sOF[r * 20 + j * 4]);
            __stwt(reinterpret_cast<float4*>(
                &out[(size_t)t * (BATCH * DOUT) + (size_t)(m0 + r) * DOUT + nt * 16 + j * 4]), v);
        }
        if (tid == 0 && !last) {
            unsigned tgt = (unsigned)(t + 1) * (GRID_LSTM / 2);
            while (*barp < tgt) { }
            __threadfence();
        }
        __syncthreads();
    }
}

// ---------------- launch ----------------
extern "C" void kernel_launch(void* const* d_in, const int* in_sizes, int n_in,
                              void* d_out, int out_size) {
    const float* tokens = (const float*)d_in[0];
    const float* Wf = (const float*)d_in[1]; const float* bf = (const float*)d_in[2];
    const float* Wi = (const float*)d_in[3]; const float* bi = (const float*)d_in[4];
    const float* Wc = (const float*)d_in[5]; const float* bc = (const float*)d_in[6];
    const float* Wo = (const float*)d_in[7]; const float* bo = (const float*)d_in[8];

    cudaFuncSetAttribute(precompute_fp16, cudaFuncAttributeMaxDynamicSharedMemorySize, PC_SMEM);
    cudaFuncSetAttribute(lstm_fp16,       cudaFuncAttributeMaxDynamicSharedMemorySize, LS_SMEM);

    pack_kernel<<<2048, 256>>>(tokens, Wf, bf, Wi, bi, Wc, bc, Wo, bo);
    precompute_fp16<<<512 * 32, 256, PC_SMEM>>>();
    lstm_fp16<<<GRID_LSTM, 512, LS_SMEM>>>((float*)d_out);
}

// round 14
// speedup vs baseline: 1.1634x; 1.0182x over previous
#include <cuda_runtime.h>
#include <cuda_fp16.h>
#include <cstdint>
#include <cstddef>

#define T_SEQ 512
#define BATCH 128
#define DIN   1024
#define DOUT  1024
#define N4    4096          // 4 gates * DOUT, gate-interleaved: n = unit*4 + gate
#define GRID_LSTM 128

// ---------------- static device scratch (no allocations allowed) ----------------
__device__ __align__(256) __half g_ZH  [(size_t)T_SEQ * BATCH * N4]; // 512 MiB fp16 preactivations (x-part + bias)
__device__ __align__(256) __half g_WxH [(size_t)N4 * DIN];           // packed fp16 x-weights
__device__ __align__(256) __half g_WhH [(size_t)N4 * DOUT];          // packed fp16 h-weights
__device__ __align__(256) float  g_bias[N4];
__device__ __align__(256) __half g_XhH [(size_t)T_SEQ * BATCH * DIN];// fp16 tokens
__device__ __align__(256) __half g_hH  [2][BATCH * DOUT];            // ping-pong hidden state fp16
__device__ unsigned g_bar2[2][32];                                   // per-mt-group barrier counters

// ---------------- helpers ----------------
__device__ __forceinline__ void cp16(void* smem_dst, const void* gsrc) {
    unsigned s = (unsigned)__cvta_generic_to_shared(smem_dst);
    asm volatile("cp.async.cg.shared.global [%0], [%1], 16;\n" :: "r"(s), "l"(gsrc));
}

__device__ __forceinline__ void ldsm4(unsigned& r0, unsigned& r1, unsigned& r2, unsigned& r3,
                                      uint32_t addr) {
    asm volatile("ldmatrix.sync.aligned.m8n8.x4.shared.b16 {%0,%1,%2,%3}, [%4];"
                 : "=r"(r0), "=r"(r1), "=r"(r2), "=r"(r3) : "r"(addr));
}

__device__ __forceinline__ void mma16(float* d, const unsigned* a, const unsigned* b) {
    asm volatile(
        "mma.sync.aligned.m16n8k16.row.col.f32.f16.f16.f32 "
        "{%0,%1,%2,%3}, {%4,%5,%6,%7}, {%8,%9}, {%0,%1,%2,%3};\n"
        : "+f"(d[0]), "+f"(d[1]), "+f"(d[2]), "+f"(d[3])
        : "r"(a[0]), "r"(a[1]), "r"(a[2]), "r"(a[3]), "r"(b[0]), "r"(b[1]));
}

__device__ __forceinline__ float sigm(float x) { return 1.f / (1.f + __expf(-x)); }

__device__ __forceinline__ uint32_t smem_u32(const void* p) {
    return (uint32_t)__cvta_generic_to_shared(p);
}

// ---------------- kernel 1: pack weights / convert tokens / reset state ----------------
__global__ void __launch_bounds__(256) pack_kernel(
    const float* __restrict__ tokens,
    const float* __restrict__ Wf, const float* __restrict__ bf,
    const float* __restrict__ Wi, const float* __restrict__ bi,
    const float* __restrict__ Wc, const float* __restrict__ bc,
    const float* __restrict__ Wo, const float* __restrict__ bo)
{
    size_t tid = (size_t)blockIdx.x * blockDim.x + threadIdx.x;
    size_t nth = (size_t)gridDim.x * blockDim.x;
    if (tid < 64) g_bar2[tid >> 5][tid & 31] = 0;   // reset barriers every launch (graph replays)

    for (size_t i = tid; i < (size_t)N4 * 1024; i += nth) {
        int n = (int)(i >> 10), k = (int)(i & 1023);
        int u = n >> 2, g = n & 3;
        const float* W = (g == 0) ? Wf : (g == 1) ? Wi : (g == 2) ? Wc : Wo;
        g_WxH[i] = __float2half_rn(W[(size_t)u * 2048 + k]);
        g_WhH[i] = __float2half_rn(W[(size_t)u * 2048 + 1024 + k]);
    }
    for (size_t i = tid; i < (size_t)N4; i += nth) {
        int u = (int)(i >> 2), g = (int)(i & 3);
        const float* bb = (g == 0) ? bf : (g == 1) ? bi : (g == 2) ? bc : bo;
        g_bias[i] = bb[u];
    }
    for (size_t i = tid; i < (size_t)T_SEQ * BATCH * DIN; i += nth)
        g_XhH[i] = __float2half_rn(tokens[i]);
    for (size_t i = tid; i < (size_t)BATCH * DOUT; i += nth)
        g_hH[0][i] = __float2half_rn(0.f);   // h0 = 0
}

// ---------------- kernel 2: fp16 mma (f32 acc): Z = X @ Wx^T + b -> fp16 ----------------
// CTA tile 128x128, 256 threads = 8 warps 2(M)x4(N); warp tile 64x32; K-chunk 64.
// 2 CTAs/SM -> 16 warps/SM. (Measured at the legacy-HMMA pipe ceiling.)
#define PC_SAS  72                    // halfs per smem row (64 data + 8 pad)
#define PC_PT   (128 * PC_SAS)        // halfs per 128x64 tile (9216)
#define PC_SMEM (2 * 2 * PC_PT * 2)   // bytes = 73728 (A,B x double buffer)

__global__ void __launch_bounds__(256, 2) precompute_fp16() {
    extern __shared__ __half smH[];
    const int tid = threadIdx.x, lane = tid & 31, wid = tid >> 5;
    const int wm = wid >> 2, wn = wid & 3;
    const int gid = lane >> 2, tig = lane & 3;
    const int bx = blockIdx.x;
    const int mt = bx >> 5, nt = bx & 31;        // nt fastest: A tile shared in L2
    const size_t m0 = (size_t)mt * 128;
    const int n0 = nt * 128;

    const __half* Ax = g_XhH + m0 * 1024;
    const __half* Bw = g_WxH + (size_t)n0 * 1024;
    const uint32_t smb = smem_u32(smH);

    const int aR = (lane & 15), aK = ((lane >> 4) << 3);
    const int bR = (lane & 7) + ((lane >> 4) << 3), bK = ((lane >> 3) & 1) << 3;

    float acc[4][4][4] = {};

    #define PC_LOAD(buf, c) do {                                                   \
        __half* d_ = smH + (buf) * 2 * PC_PT;                                      \
        int k0_ = (c) * 64;                                                        \
        _Pragma("unroll")                                                          \
        for (int i_ = 0; i_ < 4; i_++) { int ix_ = tid + i_ * 256;                 \
            int r_ = ix_ >> 3, s_ = ix_ & 7;                                       \
            cp16(d_ + r_ * PC_SAS + s_ * 8, Ax + (size_t)r_ * 1024 + k0_ + s_ * 8);} \
        _Pragma("unroll")                                                          \
        for (int i_ = 0; i_ < 4; i_++) { int ix_ = tid + i_ * 256;                 \
            int r_ = ix_ >> 3, s_ = ix_ & 7;                                       \
            cp16(d_ + PC_PT + r_ * PC_SAS + s_ * 8, Bw + (size_t)r_ * 1024 + k0_ + s_ * 8);} \
        asm volatile("cp.async.commit_group;\n");                                  \
    } while (0)

    PC_LOAD(0, 0);

    #pragma unroll 1
    for (int c = 0; c < 16; c++) {
        asm volatile("cp.async.wait_group 0;\n");
        __syncthreads();
        if (c + 1 < 16) PC_LOAD((c + 1) & 1, c + 1);

        const uint32_t base = smb + (uint32_t)((c & 1) * 2 * PC_PT) * 2;
        #pragma unroll
        for (int kk = 0; kk < 4; kk++) {
            const int ko = kk * 16;
            unsigned bfr[4][2];
            #pragma unroll
            for (int nb = 0; nb < 2; nb++) {
                uint32_t ad = base + (uint32_t)PC_PT * 2 +
                              (uint32_t)((wn * 32 + nb * 16 + bR) * PC_SAS + ko + bK) * 2;
                ldsm4(bfr[2 * nb][0], bfr[2 * nb][1], bfr[2 * nb + 1][0], bfr[2 * nb + 1][1], ad);
            }
            unsigned af[4][4];
            #pragma unroll
            for (int mi = 0; mi < 4; mi++) {
                uint32_t ad = base + (uint32_t)((wm * 64 + mi * 16 + aR) * PC_SAS + ko + aK) * 2;
                ldsm4(af[mi][0], af[mi][1], af[mi][2], af[mi][3], ad);
            }
            #pragma unroll
            for (int mi = 0; mi < 4; mi++)
                #pragma unroll
                for (int ni = 0; ni < 4; ni++)
                    mma16(acc[mi][ni], af[mi], bfr[ni]);
        }
    }

    // epilogue: add bias, write Z as fp16 (half2 stores)
    #pragma unroll
    for (int mi = 0; mi < 4; mi++)
        #pragma unroll
        for (int ni = 0; ni < 4; ni++) {
            size_t row = m0 + wm * 64 + mi * 16 + gid;
            int col = n0 + wn * 32 + ni * 8 + 2 * tig;
            float b0 = g_bias[col], b1 = g_bias[col + 1];
            *reinterpret_cast<__half2*>(&g_ZH[row * N4 + col]) =
                __floats2half2_rn(acc[mi][ni][0] + b0, acc[mi][ni][1] + b1);
            *reinterpret_cast<__half2*>(&g_ZH[(row + 8) * N4 + col]) =
                __floats2half2_rn(acc[mi][ni][2] + b0, acc[mi][ni][3] + b1);
        }
}

// ---------------- kernel 3: persistent recurrent LSTM, 512 threads (16 warps) ----------
// 128 CTAs (2 independent mt groups x 64 nt), 64x64 tile, 16 warps 4(M)x4(N),
// warp tile 16x16. Wh resident in smem; A in 4 chunks of 256.
// Tail: hout store + barrier ARRIVE first; fp32 out store + spin in barrier shadow.
#define LS_BSAS 1032                            // halfs per resident-B row (1024 + 8 pad)
#define LS_BT   (64 * LS_BSAS)                  // 66048 halfs
#define ST_SAS  136                             // halfs per staging row (128 + 8 pad)
#define ST_BUF  (64 * ST_SAS)                   // 8704 halfs per sub-buffer
#define LS_SMEM ((LS_BT + 4 * ST_BUF) * 2)      // 201728 bytes

__global__ void __launch_bounds__(512) lstm_fp16(float* __restrict__ out) {
    extern __shared__ __half smL[];
    __half* sB = smL;                 // resident Wh slice
    __half* sA = smL + LS_BT;         // 4 staging sub-buffers (2 chunk pairs)
    float*  sOF = reinterpret_cast<float*>(sA);   // out-tile staging: 64 x 16 f32, stride 20 (bytes [0,5120))
    __half* sOH = sA + 2560;                      // h-tile staging: 64 x 16 f16, stride 24 (bytes [5120,8192))

    const int tid = threadIdx.x, lane = tid & 31, wid = tid >> 5;
    const int wm = wid >> 2, wn = wid & 3;       // 4(M) x 4(N)
    const int gid = lane >> 2, tig = lane & 3;
    const int bx = blockIdx.x;
    const int mt = bx >> 6, nt = bx & 63;
    const int m0 = mt * 64, n0 = nt * 64;

    const uint32_t sBb = smem_u32(sB);
    const uint32_t sAb = smem_u32(sA);
    volatile unsigned* barp = (volatile unsigned*)&g_bar2[mt][0];

    const int aR = (lane & 15), aK = ((lane >> 4) << 3);
    const int bR = (lane & 7) + ((lane >> 4) << 3), bK = ((lane >> 3) & 1) << 3;

    // preload resident Wh slice: 64 rows x 1024 halfs = 8192 cp16, 16/thread
    {
        const __half* Wb = g_WhH + (size_t)n0 * 1024;
        #pragma unroll 4
        for (int i = 0; i < 16; i++) {
            int idx = tid + i * 512;
            int r = idx >> 7, s = idx & 127;
            cp16(sB + r * LS_BSAS + s * 8, Wb + (size_t)r * 1024 + s * 8);
        }
        asm volatile("cp.async.commit_group;\n");
        asm volatile("cp.async.wait_group 0;\n");
        __syncthreads();
    }

    // c-state: even lanes hold row gid, odd lanes row gid+8; [ni]
    float cst[2] = {0.f, 0.f};
    const int odd = tig & 1;
    const int row_l = wm * 16 + gid + (odd ? 8 : 0);

    // ---- A chunk loader: 64 rows x 256 halfs = 2048 cp16, 4/thread ----
    #define LOADH(c, hin_) do {                                                     \
        int pr_ = (c) & 1;                                                          \
        __half* d_ = sA + pr_ * 2 * ST_BUF;                                         \
        const __half* sh_ = (hin_) + (size_t)m0 * 1024 + (c) * 256;                 \
        _Pragma("unroll")                                                           \
        for (int i_ = 0; i_ < 4; i_++) { int ix_ = tid + i_ * 512;                  \
            int r_ = ix_ >> 5, s_ = ix_ & 31;                                       \
            cp16(d_ + (s_ >> 4) * ST_BUF + r_ * ST_SAS + (s_ & 15) * 8,             \
                 sh_ + (size_t)r_ * 1024 + s_ * 8); }                               \
        asm volatile("cp.async.commit_group;\n");                                   \
    } while (0)

    for (int t = 0; t < T_SEQ; t++) {
        const __half* hin = g_hH[t & 1];
        __half*      hout = g_hH[(t + 1) & 1];
        const __half* ZtH = g_ZH + (size_t)t * BATCH * N4;

        // issue first two A chunks immediately
        LOADH(0, hin);
        LOADH(1, hin);

        // prefetch Z fragments (fp16, streaming; latency hides under the GEMM)
        unsigned zr[2][2];
        #pragma unroll
        for (int ni = 0; ni < 2; ni++) {
            int row = m0 + wm * 16 + gid;
            int col = n0 + wn * 16 + ni * 8 + 2 * tig;
            zr[ni][0] = __ldcs(reinterpret_cast<const unsigned*>(&ZtH[(size_t)row * N4 + col]));
            zr[ni][1] = __ldcs(reinterpret_cast<const unsigned*>(&ZtH[(size_t)(row + 8) * N4 + col]));
        }

        float acc[2][4] = {};

        #pragma unroll 1
        for (int c = 0; c < 4; c++) {
            if (c == 0) asm volatile("cp.async.wait_group 1;\n");
            else        asm volatile("cp.async.wait_group 0;\n");
            __syncthreads();
            if (c >= 1 && c + 1 < 4) LOADH(c + 1, hin);
            uint32_t ab = sAb + (uint32_t)((c & 1) * 2 * ST_BUF) * 2;
            #pragma unroll
            for (int kk = 0; kk < 16; kk++) {
                unsigned bfr[2][2];
                ldsm4(bfr[0][0], bfr[0][1], bfr[1][0], bfr[1][1],
                      sBb + (uint32_t)((wn * 16 + bR) * LS_BSAS + c * 256 + kk * 16 + bK) * 2);
                unsigned af[4];
                ldsm4(af[0], af[1], af[2], af[3],
                      ab + (uint32_t)((kk >> 3) * ST_BUF +
                           (wm * 16 + aR) * ST_SAS + (kk & 7) * 16 + aK) * 2);
                #pragma unroll
                for (int ni = 0; ni < 2; ni++)
                    mma16(acc[ni], af, bfr[ni]);
            }
        }

        // elementwise: add Z, swap with lane^1; even lane -> row gid, odd -> row gid+8
        float hres[2];
        #pragma unroll
        for (int ni = 0; ni < 2; ni++) {
            float2 z0 = __half22float2(*reinterpret_cast<__half2*>(&zr[ni][0]));
            float2 z1 = __half22float2(*reinterpret_cast<__half2*>(&zr[ni][1]));
            float v0 = acc[ni][0] + z0.x;
            float v1 = acc[ni][1] + z0.y;
            float v2 = acc[ni][2] + z1.x;
            float v3 = acc[ni][3] + z1.y;
            float p0 = __shfl_xor_sync(0xffffffffu, v0, 1);
            float p1 = __shfl_xor_sync(0xffffffffu, v1, 1);
            float p2 = __shfl_xor_sync(0xffffffffu, v2, 1);
            float p3 = __shfl_xor_sync(0xffffffffu, v3, 1);
            float gf = odd ? p2 : v0;
            float gi = odd ? p3 : v1;
            float gg = odd ? v2 : p0;
            float go = odd ? v3 : p1;
            float f = sigm(gf), ii = sigm(gi), g = tanhf(gg), o = sigm(go);
            float cn = cst[ni] * f + ii * g;
            cst[ni] = cn;
            hres[ni] = o * tanhf(cn);
        }

        __syncthreads();   // all ldsm reads of sA done -> staging regions reusable

        // ---- phase 1: h (fp16) staging + store + barrier ARRIVE (critical path) ----
        #pragma unroll
        for (int ni = 0; ni < 2; ni++) {
            int u_l = wn * 4 + ni * 2 + (tig >> 1);
            sOH[row_l * 24 + u_l] = __float2half_rn(hres[ni]);
        }
        __syncthreads();
        if (tid >= 256 && tid < 384) {
            int k = tid - 256, r = k >> 1, p = k & 1;
            uint4 v = *reinterpret_cast<uint4*>(&sOH[r * 24 + p * 8]);
            *reinterpret_cast<uint4*>(&hout[(size_t)(m0 + r) * DOUT + nt * 16 + p * 8]) = v;
        }
        __syncthreads();
        const bool last = (t + 1 == T_SEQ);
        if (tid == 0 && !last) {
            __threadfence();
            atomicAdd((unsigned*)barp, 1u);
        }

        // ---- phase 2: fp32 out staging + store in the barrier shadow ----
        #pragma unroll
        for (int ni = 0; ni < 2; ni++) {
            int u_l = wn * 4 + ni * 2 + (tig >> 1);
            sOF[row_l * 20 + u_l] = hres[ni];
        }
        __syncthreads();
        if (tid < 256) {
            int r = tid >> 2, j = tid & 3;
            float4 v = *reinterpret_cast<float4*>(&sOF[r * 20 + j * 4]);
            __stwt(reinterpret_cast<float4*>(
                &out[(size_t)t * (BATCH * DOUT) + (size_t)(m0 + r) * DOUT + nt * 16 + j * 4]), v);
        }
        if (tid == 0 && !last) {
            unsigned tgt = (unsigned)(t + 1) * (GRID_LSTM / 2);
            while (*barp < tgt) { }
            __threadfence();
        }
        __syncthreads();
    }
}

// ---------------- launch ----------------
extern "C" void kernel_launch(void* const* d_in, const int* in_sizes, int n_in,
                              void* d_out, int out_size) {
    const float* tokens = (const float*)d_in[0];
    const float* Wf = (const float*)d_in[1]; const float* bf = (const float*)d_in[2];
    const float* Wi = (const float*)d_in[3]; const float* bi = (const float*)d_in[4];
    const float* Wc = (const float*)d_in[5]; const float* bc = (const float*)d_in[6];
    const float* Wo = (const float*)d_in[7]; const float* bo = (const float*)d_in[8];

    cudaFuncSetAttribute(precompute_fp16, cudaFuncAttributeMaxDynamicSharedMemorySize, PC_SMEM);
    cudaFuncSetAttribute(lstm_fp16,       cudaFuncAttributeMaxDynamicSharedMemorySize, LS_SMEM);

    pack_kernel<<<2048, 256>>>(tokens, Wf, bf, Wi, bi, Wc, bc, Wo, bo);
    precompute_fp16<<<512 * 32, 256, PC_SMEM>>>();
    lstm_fp16<<<GRID_LSTM, 512, LS_SMEM>>>((float*)d_out);
}